// round 16
// baseline (speedup 1.0000x reference)
#include <cuda_runtime.h>
#include <cuda_fp16.h>
#include <cstdint>
#include <cstddef>

#define D_IN   1024
#define NCLS   225
#define NOUT   224
#define VOCAB  50257

// ---------------- device scratch (allocation-free rule) ----------------
__device__ __half g_W2H[(size_t)NCLS * NOUT * D_IN];  // [c][n][k] fp16
__device__ __half g_Xh[1024 * D_IN];                  // X fp16, [m][k] (raw layout)
__device__ float  g_cls[1024 * NCLS];                 // class probs [n][c]

// ---------------- helpers ----------------
__device__ __forceinline__ uint32_t f2h2(float lo, float hi) {
    uint32_t u;
    asm("cvt.rn.f16x2.f32 %0, %1, %2;" : "=r"(u) : "f"(hi), "f"(lo));
    return u;
}

__device__ __forceinline__ void stg_cs(float* p, float v) {
    asm volatile("st.global.cs.f32 [%0], %1;" :: "l"(p), "f"(v) : "memory");
}

__device__ __forceinline__ uint32_t smem_u32(const void* p) {
    uint32_t a;
    asm("{ .reg .u64 t; cvta.to.shared.u64 t, %1; cvt.u32.u64 %0, t; }" : "=r"(a) : "l"(p));
    return a;
}

__device__ __forceinline__ void cp16(uint32_t s, const void* g) {
    asm volatile("cp.async.cg.shared.global [%0], [%1], 16;" :: "r"(s), "l"(g));
}
#define CP_COMMIT()  asm volatile("cp.async.commit_group;" ::: "memory")
#define CP_WAIT(n)   asm volatile("cp.async.wait_group %0;" :: "n"(n) : "memory")

__device__ __forceinline__ void ldsm4(uint32_t* r, uint32_t addr) {
    asm volatile("ldmatrix.sync.aligned.m8n8.x4.shared.b16 {%0,%1,%2,%3}, [%4];"
        : "=r"(r[0]), "=r"(r[1]), "=r"(r[2]), "=r"(r[3]) : "r"(addr));
}
__device__ __forceinline__ void ldsm2(uint32_t* r, uint32_t addr) {
    asm volatile("ldmatrix.sync.aligned.m8n8.x2.shared.b16 {%0,%1}, [%2];"
        : "=r"(r[0]), "=r"(r[1]) : "r"(addr));
}

__device__ __forceinline__ void mma_f16(float* c,
                                        uint32_t a0, uint32_t a1, uint32_t a2, uint32_t a3,
                                        uint32_t b0, uint32_t b1) {
    asm volatile(
        "mma.sync.aligned.m16n8k16.row.col.f32.f16.f16.f32 "
        "{%0,%1,%2,%3}, {%4,%5,%6,%7}, {%8,%9}, {%0,%1,%2,%3};"
        : "+f"(c[0]), "+f"(c[1]), "+f"(c[2]), "+f"(c[3])
        : "r"(a0), "r"(a1), "r"(a2), "r"(a3), "r"(b0), "r"(b1));
}

// ---------------- smem layout (main): swizzled 128B rows, K=64 halves/stage ----------------
#define NSTAGE 3
#define A_STAGE_B 8192
#define B_STAGE_B 28672
#define OFF_B     (NSTAGE * A_STAGE_B)               // 24576
#define SMEM_TOTAL (OFF_B + NSTAGE * B_STAGE_B)      // 110592 (108KB) -> 2 CTAs/SM

#define PREP_SMEM (64 * 225 * 4)                      // 57600 B dynamic

// ---------------------------------------------------------------------------
// Merged prep kernel (dynamic smem):
//   [0, 128)    : class softmax (fp32 exact), 8 rows/block -> g_cls
//   [128, 640)  : X f32 -> f16 (layout preserved)
//   [640, 4240) : W2 [c][k][n] -> g_W2H [c][n][k] f16; 64k x 224n tiles:
//                 contiguous 224KB global read, 128B-segment writes.
// ---------------------------------------------------------------------------
struct PrepCls { float4 sx4[8][256]; float slog[8][228]; };

__global__ __launch_bounds__(256) void prep_kernel(
    const float* __restrict__ X, const float* __restrict__ W1,
    const float* __restrict__ b1, const float* __restrict__ W2) {
    extern __shared__ char psm[];

    int t = threadIdx.x;
    int b = blockIdx.x;

    if (b < 128) {
        PrepCls& sh = *reinterpret_cast<PrepCls*>(psm);
        int n0 = b * 8;
        const float4* Xv = reinterpret_cast<const float4*>(X) + (size_t)n0 * 256;
#pragma unroll
        for (int i = 0; i < 8; i++) {
            int idx = t + 256 * i;
            sh.sx4[idx >> 8][idx & 255] = Xv[idx];
        }
        __syncthreads();

        int c = t;
        if (c < NCLS) {
            float acc[8];
            float bb = b1[c];
#pragma unroll
            for (int r = 0; r < 8; r++) acc[r] = bb;
            for (int q = 0; q < 256; q++) {
                float w0 = W1[(4 * q + 0) * NCLS + c];
                float w1 = W1[(4 * q + 1) * NCLS + c];
                float w2v = W1[(4 * q + 2) * NCLS + c];
                float w3 = W1[(4 * q + 3) * NCLS + c];
#pragma unroll
                for (int r = 0; r < 8; r++) {
                    float4 xv = sh.sx4[r][q];
                    acc[r] += xv.x * w0 + xv.y * w1 + xv.z * w2v + xv.w * w3;
                }
            }
#pragma unroll
            for (int r = 0; r < 8; r++) sh.slog[r][c] = acc[r];
        }
        __syncthreads();

        int w = t >> 5, l = t & 31;
        float v[8];
#pragma unroll
        for (int i = 0; i < 8; i++) {
            int cc = l + 32 * i;
            v[i] = (cc < NCLS) ? sh.slog[w][cc] : -1e30f;
        }
        float m = v[0];
#pragma unroll
        for (int i = 1; i < 8; i++) m = fmaxf(m, v[i]);
#pragma unroll
        for (int s = 16; s > 0; s >>= 1) m = fmaxf(m, __shfl_xor_sync(0xffffffffu, m, s));
        float sum = 0.f;
#pragma unroll
        for (int i = 0; i < 8; i++) {
            v[i] = __expf(v[i] - m);
            sum += v[i];
        }
#pragma unroll
        for (int s = 16; s > 0; s >>= 1) sum += __shfl_xor_sync(0xffffffffu, sum, s);
        float inv = 1.f / sum;
#pragma unroll
        for (int i = 0; i < 8; i++) {
            int cc = l + 32 * i;
            if (cc < NCLS) g_cls[(n0 + w) * NCLS + cc] = v[i] * inv;
        }
    } else if (b < 640) {
        int idx = (b - 128) * 256 + t;
        float4 v0 = reinterpret_cast<const float4*>(X)[2 * idx];
        float4 v1 = reinterpret_cast<const float4*>(X)[2 * idx + 1];
        uint4 o;
        o.x = f2h2(v0.x, v0.y);
        o.y = f2h2(v0.z, v0.w);
        o.z = f2h2(v1.x, v1.y);
        o.w = f2h2(v1.z, v1.w);
        reinterpret_cast<uint4*>(g_Xh)[idx] = o;
    } else {
        // ---- w2t: one (class, 64-k tile); contiguous read, 128B writes ----
        float* w2s = reinterpret_cast<float*>(psm);   // [64][225]
        int bw  = b - 640;          // 0..3599
        int c   = bw >> 4;          // 0..224
        int kt2 = bw & 15;          // 0..15 (64-k tiles)
        const float* Wb = W2 + ((size_t)c * D_IN + kt2 * 64) * NOUT;

        // read 64 k-rows x 224 n = 3584 float4s (fully contiguous region)
#pragma unroll
        for (int i = 0; i < 14; i++) {
            int idx = t + 256 * i;
            int kr  = idx / 56;
            int c4  = idx % 56;
            float4 v = *reinterpret_cast<const float4*>(Wb + (size_t)kr * NOUT + c4 * 4);
            float* d = w2s + kr * 225 + c4 * 4;
            d[0] = v.x; d[1] = v.y; d[2] = v.z; d[3] = v.w;
        }
        __syncthreads();

        // write 224 n-rows x 64 k-halves = 1792 uint4s; 8 threads per row -> 128B segs
#pragma unroll
        for (int i = 0; i < 7; i++) {
            int idx = t + 256 * i;
            int n   = idx >> 3;
            int q   = idx & 7;      // 8-half chunk within the 64-k row
            const float* s = w2s + (q * 8) * 225 + n;
            uint4 o;
            o.x = f2h2(s[0 * 225], s[1 * 225]);
            o.y = f2h2(s[2 * 225], s[3 * 225]);
            o.z = f2h2(s[4 * 225], s[5 * 225]);
            o.w = f2h2(s[6 * 225], s[7 * 225]);
            size_t hoff = ((size_t)c * NOUT + n) * D_IN + kt2 * 64 + q * 8;
            *reinterpret_cast<uint4*>(g_W2H + hoff) = o;
        }
    }
}

// ---------------------------------------------------------------------------
// cp.async stage loader (128 threads): K=64 halves per stage
// ---------------------------------------------------------------------------
__device__ __forceinline__ void load_stage(uint32_t sbase, int buf, int kt,
                                           int bm, int c, int t) {
    int koff = kt * 64;
    uint32_t abuf = sbase + buf * A_STAGE_B;
#pragma unroll
    for (int i = 0; i < 4; i++) {
        int idx = t + 128 * i;          // 512 chunks: 64 m x 8
        int m   = idx >> 3;
        int ch  = idx & 7;
        const __half* g = g_Xh + (size_t)(bm * 64 + m) * D_IN + koff + ch * 8;
        cp16(abuf + (uint32_t)(m * 128 + ((ch ^ (m & 7)) << 4)), g);
    }
    uint32_t bbuf = sbase + OFF_B + buf * B_STAGE_B;
#pragma unroll
    for (int i = 0; i < 14; i++) {
        int idx = t + 128 * i;          // 1792 chunks: 224 n x 8
        int n   = idx >> 3;
        int ch  = idx & 7;
        const __half* g = g_W2H + ((size_t)c * NOUT + n) * D_IN + koff + ch * 8;
        cp16(bbuf + (uint32_t)(n * 128 + ((ch ^ (n & 7)) << 4)), g);
    }
}

// ---------------------------------------------------------------------------
// Main kernel (round-10 proven best, byte-exact): 64x224xK1024 fp16 mma,
// 4 warps, 2 CTAs/SM, cross-stage fragment prefetch. grid (16, 225).
// ---------------------------------------------------------------------------
__global__ __launch_bounds__(128, 2) void hsm_main_kernel(
    const float* __restrict__ b2, float* __restrict__ out) {
    extern __shared__ float smem[];
    uint32_t sbase = smem_u32(smem);

    int t    = threadIdx.x;
    int bm   = blockIdx.x;          // 0..15 (64-row m tiles)
    int c    = blockIdx.y;          // 0..224
    int wn   = t >> 5, l = t & 31;  // 4 warps, all N-split
    int lq = l & 3, lr = l >> 2;

    // ldmatrix per-lane constants
    const uint32_t r7    = l & 7;
    const uint32_t aRow0 = ((l >> 3) & 1) * 8 + r7;             // + 16*mf
    const uint32_t kbA   = (l >> 4) & 1;                         // k8-half select
    const uint32_t bRow0 = wn * 56 + ((l >> 4) & 1) * 8 + r7;   // + 16*p
    const uint32_t kbB   = (l >> 3) & 1;
    const uint32_t bRow2 = wn * 56 + 48 + r7;                   // nf=6 (x2)

    float acc[4][7][4];
#pragma unroll
    for (int mf = 0; mf < 4; mf++)
#pragma unroll
        for (int nf = 0; nf < 7; nf++)
#pragma unroll
            for (int i = 0; i < 4; i++) acc[mf][nf][i] = 0.f;

    // prologue: fill 2 stages
#pragma unroll
    for (int s = 0; s < 2; s++) {
        load_stage(sbase, s, s, bm, c, t);
        CP_COMMIT();
    }
    CP_WAIT(1);                 // stage 0 resident
    __syncthreads();

    const int KT = D_IN / 64;   // 16 stages, 4 k16-steps each
    uint32_t a[2][4][4], b[2][7][2];
    int buf = 0;

    // preload ks0 fragments of stage 0
    {
        uint32_t aS = sbase;
        uint32_t bS = sbase + OFF_B;
        uint32_t qA = ((kbA ^ r7) << 4);
        uint32_t qB = ((kbB ^ r7) << 4);
#pragma unroll
        for (int mf = 0; mf < 4; mf++)
            ldsm4(a[0][mf], aS + (aRow0 + 16 * mf) * 128 + qA);
#pragma unroll
        for (int p = 0; p < 3; p++)
            ldsm4(&b[0][2 * p][0], bS + (bRow0 + 16 * p) * 128 + qB);
        ldsm2(&b[0][6][0], bS + bRow2 * 128 + qB);
    }

    for (int kt = 0; kt < KT; kt++) {
        uint32_t aS = sbase + buf * A_STAGE_B;
        uint32_t bS = sbase + OFF_B + buf * B_STAGE_B;

        // ks = 0..2: load frags ks+1, mma ks
#pragma unroll
        for (int ks = 0; ks < 3; ks++) {
            int cur = ks & 1, nxt = cur ^ 1;
            uint32_t qA = (((2 * (ks + 1) + kbA) ^ r7) << 4);
            uint32_t qB = (((2 * (ks + 1) + kbB) ^ r7) << 4);
#pragma unroll
            for (int mf = 0; mf < 4; mf++)
                ldsm4(a[nxt][mf], aS + (aRow0 + 16 * mf) * 128 + qA);
#pragma unroll
            for (int p = 0; p < 3; p++)
                ldsm4(&b[nxt][2 * p][0], bS + (bRow0 + 16 * p) * 128 + qB);
            ldsm2(&b[nxt][6][0], bS + bRow2 * 128 + qB);
#pragma unroll
            for (int nf = 0; nf < 7; nf++)
#pragma unroll
                for (int mf = 0; mf < 4; mf++)
                    mma_f16(acc[mf][nf], a[cur][mf][0], a[cur][mf][1],
                            a[cur][mf][2], a[cur][mf][3], b[cur][nf][0], b[cur][nf][1]);
        }

        // stage boundary, hidden behind ks=3's mma batch
        if (kt + 2 < KT) {
            int nb = buf + 2; if (nb >= NSTAGE) nb -= NSTAGE;
            load_stage(sbase, nb, kt + 2, bm, c, t);
        }
        CP_COMMIT();            // unconditional: keeps group accounting
        CP_WAIT(1);             // stage kt+1 resident
        __syncthreads();        // all warps' copies visible; reads of old bufs done

        // prefetch ks0 fragments of stage kt+1 (slot 0; ks3 uses slot 1)
        {
            int nb1 = buf + 1; if (nb1 >= NSTAGE) nb1 -= NSTAGE;
            uint32_t aN = sbase + nb1 * A_STAGE_B;
            uint32_t bN = sbase + OFF_B + nb1 * B_STAGE_B;
            uint32_t qA = ((kbA ^ r7) << 4);
            uint32_t qB = ((kbB ^ r7) << 4);
#pragma unroll
            for (int mf = 0; mf < 4; mf++)
                ldsm4(a[0][mf], aN + (aRow0 + 16 * mf) * 128 + qA);
#pragma unroll
            for (int p = 0; p < 3; p++)
                ldsm4(&b[0][2 * p][0], bN + (bRow0 + 16 * p) * 128 + qB);
            ldsm2(&b[0][6][0], bN + bRow2 * 128 + qB);
            buf = nb1;
        }

        // ks = 3 mma from registers (overlaps the prefetch above)
#pragma unroll
        for (int nf = 0; nf < 7; nf++)
#pragma unroll
            for (int mf = 0; mf < 4; mf++)
                mma_f16(acc[mf][nf], a[1][mf][0], a[1][mf][1],
                        a[1][mf][2], a[1][mf][3], b[1][nf][0], b[1][nf][1]);
    }

    // ---- fused softmax epilogue, no max pass ----
    __syncthreads();
    float* reds = smem;             // [64][4]

    const float* b2c = b2 + (size_t)c * NOUT;
    const int colbase = wn * 56 + 2 * lq;
    float b2v[7][2];
#pragma unroll
    for (int nf = 0; nf < 7; nf++) {
        b2v[nf][0] = b2c[colbase + nf * 8];
        b2v[nf][1] = b2c[colbase + nf * 8 + 1];
    }

    float sm[4][2];
#pragma unroll
    for (int mf = 0; mf < 4; mf++) { sm[mf][0] = 0.f; sm[mf][1] = 0.f; }
#pragma unroll
    for (int mf = 0; mf < 4; mf++)
#pragma unroll
        for (int nf = 0; nf < 7; nf++) {
            acc[mf][nf][0] = __expf(acc[mf][nf][0] + b2v[nf][0]); sm[mf][0] += acc[mf][nf][0];
            acc[mf][nf][1] = __expf(acc[mf][nf][1] + b2v[nf][1]); sm[mf][0] += acc[mf][nf][1];
            acc[mf][nf][2] = __expf(acc[mf][nf][2] + b2v[nf][0]); sm[mf][1] += acc[mf][nf][2];
            acc[mf][nf][3] = __expf(acc[mf][nf][3] + b2v[nf][1]); sm[mf][1] += acc[mf][nf][3];
        }
#pragma unroll
    for (int mf = 0; mf < 4; mf++)
#pragma unroll
        for (int h = 0; h < 2; h++) {
            sm[mf][h] += __shfl_xor_sync(0xffffffffu, sm[mf][h], 1);
            sm[mf][h] += __shfl_xor_sync(0xffffffffu, sm[mf][h], 2);
        }
    if (lq == 0) {
#pragma unroll
        for (int mf = 0; mf < 4; mf++)
#pragma unroll
            for (int h = 0; h < 2; h++)
                reds[(mf * 16 + lr + 8 * h) * 4 + wn] = sm[mf][h];
    }
    __syncthreads();

    float scl[4][2];
#pragma unroll
    for (int mf = 0; mf < 4; mf++)
#pragma unroll
        for (int h = 0; h < 2; h++) {
            int r = mf * 16 + lr + 8 * h;
            const float* p = reds + r * 4;
            float denom = (p[0] + p[1]) + (p[2] + p[3]);
            int n = bm * 64 + r;
            scl[mf][h] = g_cls[n * NCLS + c] / denom;
        }

#pragma unroll
    for (int mf = 0; mf < 4; mf++)
#pragma unroll
        for (int h = 0; h < 2; h++) {
            int n = bm * 64 + mf * 16 + lr + 8 * h;
            float* orow = out + (size_t)n * VOCAB;
#pragma unroll
            for (int nf = 0; nf < 7; nf++) {
                int gc = c * NOUT + colbase + nf * 8;
                float v0 = acc[mf][nf][2 * h]     * scl[mf][h];
                float v1 = acc[mf][nf][2 * h + 1] * scl[mf][h];
                if (gc + 1 < VOCAB) {
                    stg_cs(orow + gc,     v0);
                    stg_cs(orow + gc + 1, v1);
                } else if (gc < VOCAB) {
                    stg_cs(orow + gc, v0);
                }
            }
        }
}

// ---------------------------------------------------------------------------
extern "C" void kernel_launch(void* const* d_in, const int* in_sizes, int n_in,
                              void* d_out, int out_size) {
    const float* X  = (const float*)d_in[0];
    const float* W1 = (const float*)d_in[1];
    const float* b1 = (const float*)d_in[2];
    const float* W2 = (const float*)d_in[3];
    const float* b2 = (const float*)d_in[4];
    float* out = (float*)d_out;

    cudaFuncSetAttribute(prep_kernel,
                         cudaFuncAttributeMaxDynamicSharedMemorySize, PREP_SMEM);
    cudaFuncSetAttribute(hsm_main_kernel,
                         cudaFuncAttributeMaxDynamicSharedMemorySize, SMEM_TOTAL);

    prep_kernel<<<4240, 256, PREP_SMEM>>>(X, W1, b1, W2);
    hsm_main_kernel<<<dim3(16, NCLS), 128, SMEM_TOTAL>>>(b2, out);
}

// round 17
// speedup vs baseline: 1.1296x; 1.1296x over previous
#include <cuda_runtime.h>
#include <cuda_fp16.h>
#include <cstdint>
#include <cstddef>

#define D_IN   1024
#define NCLS   225
#define NOUT   224
#define VOCAB  50257

// ---------------- device scratch (allocation-free rule) ----------------
__device__ __half g_W2H[(size_t)NCLS * NOUT * D_IN];  // [c][n][k] fp16
__device__ __half g_Xh[1024 * D_IN];                  // X fp16, [m][k] (raw layout)
__device__ float  g_clsT[NCLS * 1024];                // class probs [c][n] (coalesced reads)

// ---------------- helpers ----------------
__device__ __forceinline__ uint32_t f2h2(float lo, float hi) {
    uint32_t u;
    asm("cvt.rn.f16x2.f32 %0, %1, %2;" : "=r"(u) : "f"(hi), "f"(lo));
    return u;
}

__device__ __forceinline__ void stg_cs(float* p, float v) {
    asm volatile("st.global.cs.f32 [%0], %1;" :: "l"(p), "f"(v) : "memory");
}

__device__ __forceinline__ uint32_t smem_u32(const void* p) {
    uint32_t a;
    asm("{ .reg .u64 t; cvta.to.shared.u64 t, %1; cvt.u32.u64 %0, t; }" : "=r"(a) : "l"(p));
    return a;
}

__device__ __forceinline__ void cp16(uint32_t s, const void* g) {
    asm volatile("cp.async.cg.shared.global [%0], [%1], 16;" :: "r"(s), "l"(g));
}
#define CP_COMMIT()  asm volatile("cp.async.commit_group;" ::: "memory")
#define CP_WAIT(n)   asm volatile("cp.async.wait_group %0;" :: "n"(n) : "memory")

__device__ __forceinline__ void ldsm4(uint32_t* r, uint32_t addr) {
    asm volatile("ldmatrix.sync.aligned.m8n8.x4.shared.b16 {%0,%1,%2,%3}, [%4];"
        : "=r"(r[0]), "=r"(r[1]), "=r"(r[2]), "=r"(r[3]) : "r"(addr));
}
__device__ __forceinline__ void ldsm2(uint32_t* r, uint32_t addr) {
    asm volatile("ldmatrix.sync.aligned.m8n8.x2.shared.b16 {%0,%1}, [%2];"
        : "=r"(r[0]), "=r"(r[1]) : "r"(addr));
}

__device__ __forceinline__ void mma_f16(float* c,
                                        uint32_t a0, uint32_t a1, uint32_t a2, uint32_t a3,
                                        uint32_t b0, uint32_t b1) {
    asm volatile(
        "mma.sync.aligned.m16n8k16.row.col.f32.f16.f16.f32 "
        "{%0,%1,%2,%3}, {%4,%5,%6,%7}, {%8,%9}, {%0,%1,%2,%3};"
        : "+f"(c[0]), "+f"(c[1]), "+f"(c[2]), "+f"(c[3])
        : "r"(a0), "r"(a1), "r"(a2), "r"(a3), "r"(b0), "r"(b1));
}

// ---------------- smem layout (main): swizzled 128B rows, K=64 halves/stage ----------------
#define NSTAGE 3
#define A_STAGE_B 8192
#define B_STAGE_B 28672
#define OFF_B     (NSTAGE * A_STAGE_B)               // 24576
#define SMEM_TOTAL (OFF_B + NSTAGE * B_STAGE_B)      // 110592 (108KB) -> 2 CTAs/SM

// ---------------------------------------------------------------------------
// Merged prep kernel (round-10 proven layout):
//   [0, 128)   : class softmax (fp32 exact), 8 rows/block -> g_clsT[c][n]
//   [128, 640) : X f32 -> f16 (layout preserved)
//   [640, 7840): W2 [c][k][n] f32 -> g_W2H [c][n][k] f16 (transpose+convert)
// ---------------------------------------------------------------------------
__global__ __launch_bounds__(256) void prep_kernel(
    const float* __restrict__ X, const float* __restrict__ W1,
    const float* __restrict__ b1, const float* __restrict__ W2) {
    __shared__ union {
        struct { float4 sx4[8][256]; float slog[8][228]; } cls;
        float w2[32 * 225];
    } sh;

    int t = threadIdx.x;
    int b = blockIdx.x;

    if (b < 128) {
        int n0 = b * 8;
        const float4* Xv = reinterpret_cast<const float4*>(X) + (size_t)n0 * 256;
#pragma unroll
        for (int i = 0; i < 8; i++) {
            int idx = t + 256 * i;
            sh.cls.sx4[idx >> 8][idx & 255] = Xv[idx];
        }
        __syncthreads();

        int c = t;
        if (c < NCLS) {
            float acc[8];
            float bb = b1[c];
#pragma unroll
            for (int r = 0; r < 8; r++) acc[r] = bb;
            for (int q = 0; q < 256; q++) {
                float w0 = W1[(4 * q + 0) * NCLS + c];
                float w1 = W1[(4 * q + 1) * NCLS + c];
                float w2v = W1[(4 * q + 2) * NCLS + c];
                float w3 = W1[(4 * q + 3) * NCLS + c];
#pragma unroll
                for (int r = 0; r < 8; r++) {
                    float4 xv = sh.cls.sx4[r][q];
                    acc[r] += xv.x * w0 + xv.y * w1 + xv.z * w2v + xv.w * w3;
                }
            }
#pragma unroll
            for (int r = 0; r < 8; r++) sh.cls.slog[r][c] = acc[r];
        }
        __syncthreads();

        int w = t >> 5, l = t & 31;
        float v[8];
#pragma unroll
        for (int i = 0; i < 8; i++) {
            int cc = l + 32 * i;
            v[i] = (cc < NCLS) ? sh.cls.slog[w][cc] : -1e30f;
        }
        float m = v[0];
#pragma unroll
        for (int i = 1; i < 8; i++) m = fmaxf(m, v[i]);
#pragma unroll
        for (int s = 16; s > 0; s >>= 1) m = fmaxf(m, __shfl_xor_sync(0xffffffffu, m, s));
        float sum = 0.f;
#pragma unroll
        for (int i = 0; i < 8; i++) {
            v[i] = __expf(v[i] - m);
            sum += v[i];
        }
#pragma unroll
        for (int s = 16; s > 0; s >>= 1) sum += __shfl_xor_sync(0xffffffffu, sum, s);
        float inv = 1.f / sum;
#pragma unroll
        for (int i = 0; i < 8; i++) {
            int cc = l + 32 * i;
            if (cc < NCLS) g_clsT[cc * 1024 + n0 + w] = v[i] * inv;
        }
    } else if (b < 640) {
        int idx = (b - 128) * 256 + t;
        float4 v0 = reinterpret_cast<const float4*>(X)[2 * idx];
        float4 v1 = reinterpret_cast<const float4*>(X)[2 * idx + 1];
        uint4 o;
        o.x = f2h2(v0.x, v0.y);
        o.y = f2h2(v0.z, v0.w);
        o.z = f2h2(v1.x, v1.y);
        o.w = f2h2(v1.z, v1.w);
        reinterpret_cast<uint4*>(g_Xh)[idx] = o;
    } else {
        int bw = b - 640;
        int c  = bw >> 5;
        int kt = bw & 31;
        const float* Wb = W2 + ((size_t)c * D_IN + kt * 32) * NOUT;

#pragma unroll
        for (int i = 0; i < 7; i++) {
            int idx = t + 256 * i;
            int kr  = idx / 56;
            int c4  = idx % 56;
            float4 v = *reinterpret_cast<const float4*>(Wb + (size_t)kr * NOUT + c4 * 4);
            float* d = sh.w2 + kr * 225 + c4 * 4;
            d[0] = v.x; d[1] = v.y; d[2] = v.z; d[3] = v.w;
        }
        __syncthreads();

#pragma unroll
        for (int i = 0; i < 4; i++) {
            int idx = t + 256 * i;
            if (idx < 896) {
                int n  = idx >> 2;
                int qq = idx & 3;
                uint4 o;
                o.x = f2h2(sh.w2[(qq * 8 + 0) * 225 + n], sh.w2[(qq * 8 + 1) * 225 + n]);
                o.y = f2h2(sh.w2[(qq * 8 + 2) * 225 + n], sh.w2[(qq * 8 + 3) * 225 + n]);
                o.z = f2h2(sh.w2[(qq * 8 + 4) * 225 + n], sh.w2[(qq * 8 + 5) * 225 + n]);
                o.w = f2h2(sh.w2[(qq * 8 + 6) * 225 + n], sh.w2[(qq * 8 + 7) * 225 + n]);
                size_t hoff = ((size_t)c * NOUT + n) * D_IN + kt * 32 + qq * 8;
                *reinterpret_cast<uint4*>(g_W2H + hoff) = o;
            }
        }
    }
}

// ---------------------------------------------------------------------------
// cp.async stage loader (128 threads): K=64 halves per stage
// ---------------------------------------------------------------------------
__device__ __forceinline__ void load_stage(uint32_t sbase, int buf, int kt,
                                           int bm, int c, int t) {
    int koff = kt * 64;
    uint32_t abuf = sbase + buf * A_STAGE_B;
#pragma unroll
    for (int i = 0; i < 4; i++) {
        int idx = t + 128 * i;          // 512 chunks: 64 m x 8
        int m   = idx >> 3;
        int ch  = idx & 7;
        const __half* g = g_Xh + (size_t)(bm * 64 + m) * D_IN + koff + ch * 8;
        cp16(abuf + (uint32_t)(m * 128 + ((ch ^ (m & 7)) << 4)), g);
    }
    uint32_t bbuf = sbase + OFF_B + buf * B_STAGE_B;
#pragma unroll
    for (int i = 0; i < 14; i++) {
        int idx = t + 128 * i;          // 1792 chunks: 224 n x 8
        int n   = idx >> 3;
        int ch  = idx & 7;
        const __half* g = g_W2H + ((size_t)c * NOUT + n) * D_IN + koff + ch * 8;
        cp16(bbuf + (uint32_t)(n * 128 + ((ch ^ (n & 7)) << 4)), g);
    }
}

// ---------------------------------------------------------------------------
// Main kernel (round-10 proven best, byte-exact except g_clsT read):
// 64x224xK1024 fp16 mma, 4 warps, 2 CTAs/SM, cross-stage fragment prefetch.
// grid (16, 225), 128 threads.
// ---------------------------------------------------------------------------
__global__ __launch_bounds__(128, 2) void hsm_main_kernel(
    const float* __restrict__ b2, float* __restrict__ out) {
    extern __shared__ float smem[];
    uint32_t sbase = smem_u32(smem);

    int t    = threadIdx.x;
    int bm   = blockIdx.x;          // 0..15 (64-row m tiles)
    int c    = blockIdx.y;          // 0..224
    int wn   = t >> 5, l = t & 31;  // 4 warps, all N-split
    int lq = l & 3, lr = l >> 2;

    // ldmatrix per-lane constants
    const uint32_t r7    = l & 7;
    const uint32_t aRow0 = ((l >> 3) & 1) * 8 + r7;             // + 16*mf
    const uint32_t kbA   = (l >> 4) & 1;                         // k8-half select
    const uint32_t bRow0 = wn * 56 + ((l >> 4) & 1) * 8 + r7;   // + 16*p
    const uint32_t kbB   = (l >> 3) & 1;
    const uint32_t bRow2 = wn * 56 + 48 + r7;                   // nf=6 (x2)

    float acc[4][7][4];
#pragma unroll
    for (int mf = 0; mf < 4; mf++)
#pragma unroll
        for (int nf = 0; nf < 7; nf++)
#pragma unroll
            for (int i = 0; i < 4; i++) acc[mf][nf][i] = 0.f;

    // prologue: fill 2 stages
#pragma unroll
    for (int s = 0; s < 2; s++) {
        load_stage(sbase, s, s, bm, c, t);
        CP_COMMIT();
    }
    CP_WAIT(1);                 // stage 0 resident
    __syncthreads();

    const int KT = D_IN / 64;   // 16 stages, 4 k16-steps each
    uint32_t a[2][4][4], b[2][7][2];
    int buf = 0;

    // preload ks0 fragments of stage 0
    {
        uint32_t aS = sbase;
        uint32_t bS = sbase + OFF_B;
        uint32_t qA = ((kbA ^ r7) << 4);
        uint32_t qB = ((kbB ^ r7) << 4);
#pragma unroll
        for (int mf = 0; mf < 4; mf++)
            ldsm4(a[0][mf], aS + (aRow0 + 16 * mf) * 128 + qA);
#pragma unroll
        for (int p = 0; p < 3; p++)
            ldsm4(&b[0][2 * p][0], bS + (bRow0 + 16 * p) * 128 + qB);
        ldsm2(&b[0][6][0], bS + bRow2 * 128 + qB);
    }

    for (int kt = 0; kt < KT; kt++) {
        uint32_t aS = sbase + buf * A_STAGE_B;
        uint32_t bS = sbase + OFF_B + buf * B_STAGE_B;

        // ks = 0..2: load frags ks+1, mma ks
#pragma unroll
        for (int ks = 0; ks < 3; ks++) {
            int cur = ks & 1, nxt = cur ^ 1;
            uint32_t qA = (((2 * (ks + 1) + kbA) ^ r7) << 4);
            uint32_t qB = (((2 * (ks + 1) + kbB) ^ r7) << 4);
#pragma unroll
            for (int mf = 0; mf < 4; mf++)
                ldsm4(a[nxt][mf], aS + (aRow0 + 16 * mf) * 128 + qA);
#pragma unroll
            for (int p = 0; p < 3; p++)
                ldsm4(&b[nxt][2 * p][0], bS + (bRow0 + 16 * p) * 128 + qB);
            ldsm2(&b[nxt][6][0], bS + bRow2 * 128 + qB);
#pragma unroll
            for (int nf = 0; nf < 7; nf++)
#pragma unroll
                for (int mf = 0; mf < 4; mf++)
                    mma_f16(acc[mf][nf], a[cur][mf][0], a[cur][mf][1],
                            a[cur][mf][2], a[cur][mf][3], b[cur][nf][0], b[cur][nf][1]);
        }

        // stage boundary, hidden behind ks=3's mma batch
        if (kt + 2 < KT) {
            int nb = buf + 2; if (nb >= NSTAGE) nb -= NSTAGE;
            load_stage(sbase, nb, kt + 2, bm, c, t);
        }
        CP_COMMIT();            // unconditional: keeps group accounting
        CP_WAIT(1);             // stage kt+1 resident
        __syncthreads();        // all warps' copies visible; reads of old bufs done

        // prefetch ks0 fragments of stage kt+1 (slot 0; ks3 uses slot 1)
        {
            int nb1 = buf + 1; if (nb1 >= NSTAGE) nb1 -= NSTAGE;
            uint32_t aN = sbase + nb1 * A_STAGE_B;
            uint32_t bN = sbase + OFF_B + nb1 * B_STAGE_B;
            uint32_t qA = ((kbA ^ r7) << 4);
            uint32_t qB = ((kbB ^ r7) << 4);
#pragma unroll
            for (int mf = 0; mf < 4; mf++)
                ldsm4(a[0][mf], aN + (aRow0 + 16 * mf) * 128 + qA);
#pragma unroll
            for (int p = 0; p < 3; p++)
                ldsm4(&b[0][2 * p][0], bN + (bRow0 + 16 * p) * 128 + qB);
            ldsm2(&b[0][6][0], bN + bRow2 * 128 + qB);
            buf = nb1;
        }

        // ks = 3 mma from registers (overlaps the prefetch above)
#pragma unroll
        for (int nf = 0; nf < 7; nf++)
#pragma unroll
            for (int mf = 0; mf < 4; mf++)
                mma_f16(acc[mf][nf], a[1][mf][0], a[1][mf][1],
                        a[1][mf][2], a[1][mf][3], b[1][nf][0], b[1][nf][1]);
    }

    // ---- fused softmax epilogue, no max pass ----
    __syncthreads();
    float* reds = smem;             // [64][4]

    const float* b2c = b2 + (size_t)c * NOUT;
    const int colbase = wn * 56 + 2 * lq;
    float b2v[7][2];
#pragma unroll
    for (int nf = 0; nf < 7; nf++) {
        b2v[nf][0] = b2c[colbase + nf * 8];
        b2v[nf][1] = b2c[colbase + nf * 8 + 1];
    }

    float sm[4][2];
#pragma unroll
    for (int mf = 0; mf < 4; mf++) { sm[mf][0] = 0.f; sm[mf][1] = 0.f; }
#pragma unroll
    for (int mf = 0; mf < 4; mf++)
#pragma unroll
        for (int nf = 0; nf < 7; nf++) {
            acc[mf][nf][0] = __expf(acc[mf][nf][0] + b2v[nf][0]); sm[mf][0] += acc[mf][nf][0];
            acc[mf][nf][1] = __expf(acc[mf][nf][1] + b2v[nf][1]); sm[mf][0] += acc[mf][nf][1];
            acc[mf][nf][2] = __expf(acc[mf][nf][2] + b2v[nf][0]); sm[mf][1] += acc[mf][nf][2];
            acc[mf][nf][3] = __expf(acc[mf][nf][3] + b2v[nf][1]); sm[mf][1] += acc[mf][nf][3];
        }
#pragma unroll
    for (int mf = 0; mf < 4; mf++)
#pragma unroll
        for (int h = 0; h < 2; h++) {
            sm[mf][h] += __shfl_xor_sync(0xffffffffu, sm[mf][h], 1);
            sm[mf][h] += __shfl_xor_sync(0xffffffffu, sm[mf][h], 2);
        }
    if (lq == 0) {
#pragma unroll
        for (int mf = 0; mf < 4; mf++)
#pragma unroll
            for (int h = 0; h < 2; h++)
                reds[(mf * 16 + lr + 8 * h) * 4 + wn] = sm[mf][h];
    }
    __syncthreads();

    float scl[4][2];
#pragma unroll
    for (int mf = 0; mf < 4; mf++)
#pragma unroll
        for (int h = 0; h < 2; h++) {
            int r = mf * 16 + lr + 8 * h;
            const float* p = reds + r * 4;
            float denom = (p[0] + p[1]) + (p[2] + p[3]);
            int n = bm * 64 + r;
            scl[mf][h] = g_clsT[c * 1024 + n] / denom;
        }

#pragma unroll
    for (int mf = 0; mf < 4; mf++)
#pragma unroll
        for (int h = 0; h < 2; h++) {
            int n = bm * 64 + mf * 16 + lr + 8 * h;
            float* orow = out + (size_t)n * VOCAB;
#pragma unroll
            for (int nf = 0; nf < 7; nf++) {
                int gc = c * NOUT + colbase + nf * 8;
                float v0 = acc[mf][nf][2 * h]     * scl[mf][h];
                float v1 = acc[mf][nf][2 * h + 1] * scl[mf][h];
                if (gc + 1 < VOCAB) {
                    stg_cs(orow + gc,     v0);
                    stg_cs(orow + gc + 1, v1);
                } else if (gc < VOCAB) {
                    stg_cs(orow + gc, v0);
                }
            }
        }
}

// ---------------------------------------------------------------------------
extern "C" void kernel_launch(void* const* d_in, const int* in_sizes, int n_in,
                              void* d_out, int out_size) {
    const float* X  = (const float*)d_in[0];
    const float* W1 = (const float*)d_in[1];
    const float* b1 = (const float*)d_in[2];
    const float* W2 = (const float*)d_in[3];
    const float* b2 = (const float*)d_in[4];
    float* out = (float*)d_out;

    cudaFuncSetAttribute(hsm_main_kernel,
                         cudaFuncAttributeMaxDynamicSharedMemorySize, SMEM_TOTAL);

    prep_kernel<<<7840, 256>>>(X, W1, b1, W2);
    hsm_main_kernel<<<dim3(16, NCLS), 128, SMEM_TOTAL>>>(b2, out);
}